// round 1
// baseline (speedup 1.0000x reference)
#include <cuda_runtime.h>
#include <cstdint>

#define HH   128
#define WWD  128
#define HWI  (HH*WWD)
#define CIN  1024
#define CMID 512
#define KKT  9216          // CIN * 9
#define NAA  9
#define NANCH (HWI*NAA)    // 147456
#define PRE  6000
#define POST 300
#define NW   94            // ceil(6000/64)
#define LOC_OFF (NANCH*2)          // 294912
#define ROI_OFF (NANCH*2 + NANCH*4) // 884736

struct Ctrl {
    unsigned b1;
    unsigned cAbove1;
    unsigned thresholdKey;
    int      candCount;
};

// ---- static device scratch (no allocations allowed) ----
__device__ __align__(16) float g_Ar[KKT*CMID];        // 18.9 MB reordered conv weights [k][co]
__device__ __align__(16) float g_feat[CMID*HWI];      // 32 MB conv output (relu'd)
__device__ float4 g_boxes4[NANCH];                    // decoded + clipped boxes
__device__ unsigned g_key[NANCH];                     // ordered-uint score keys
__device__ unsigned g_hist1[4096];
__device__ unsigned g_hist2[4096];
__device__ unsigned long long g_cand[8192];
__device__ float4 g_sorted[PRE];                      // boxes in top-k order
__device__ unsigned long long g_mask[(size_t)PRE*NW]; // 4.5 MB IoU suppression bitmask
__device__ unsigned long long g_keep[NW];
__device__ Ctrl g_ctrl;

// =====================================================================
// 0) zero control buffers (graph replays must be deterministic)
// =====================================================================
__global__ void zero_ctrl_k() {
    int t = blockIdx.x*blockDim.x + threadIdx.x;
    if (t < 4096) { g_hist1[t] = 0; g_hist2[t] = 0; }
    if (t == 0) { g_ctrl.candCount = 0; g_ctrl.b1 = 0; g_ctrl.cAbove1 = 0; g_ctrl.thresholdKey = 0; }
}

// =====================================================================
// 1) reorder W_conv [co][ci][kh][kw] -> g_Ar[k][co], k = (kh*3+kw)*1024+ci
// =====================================================================
__global__ void reorder_w(const float* __restrict__ Wc) {
    int k = blockIdx.x;
    int g = k >> 10, ci = k & 1023;
    int kh = g / 3, kw = g - kh*3;
    for (int co = threadIdx.x; co < CMID; co += blockDim.x)
        g_Ar[k*CMID + co] = Wc[((co*CIN + ci)*3 + kh)*3 + kw];
}

// =====================================================================
// 2) conv as implicit GEMM: M=512 (co), N=16384 (p=h*128+w), K=9216
//    BM=128 BN=128 BK=8, 256 threads, 8x8 per thread. Bias + ReLU fused.
//    N-tile = one image row h so the im2col slice is contiguous w/ halo.
// =====================================================================
__global__ __launch_bounds__(256, 2)
void conv_gemm(const float* __restrict__ X, const float* __restrict__ bconv) {
    __shared__ float As[8][128];
    __shared__ float Bs[8][128];
    int h = blockIdx.x;
    int coBase = blockIdx.y * 128;
    int tid = threadIdx.x;
    int ty = tid >> 4, tx = tid & 15;
    int kl = tid >> 5;           // 0..7
    int l4 = (tid & 31) << 2;    // 0..124 step 4

    float c[8][8];
#pragma unroll
    for (int i = 0; i < 8; i++)
#pragma unroll
        for (int j = 0; j < 8; j++) c[i][j] = 0.f;

    for (int k0 = 0; k0 < KKT; k0 += 8) {
        // A tile (weights): coalesced float4
        float4 av = *(const float4*)&g_Ar[(k0 + kl)*CMID + coBase + l4];
        *(float4*)&As[kl][l4] = av;
        // B tile (implicit im2col): one (kh,kw) group per BK slice (8 | 1024)
        int k  = k0 + kl;
        int g  = k >> 10, ci = k & 1023;
        int kh = g / 3,  kw = g - kh*3;
        int row = h + kh - 1;
        bool rok = (row >= 0) && (row < HH);
        const float* Xp = X + ci*HWI + row*WWD;
#pragma unroll
        for (int u = 0; u < 4; u++) {
            int col = l4 + u + kw - 1;
            Bs[kl][l4 + u] = (rok && col >= 0 && col < WWD) ? Xp[col] : 0.f;
        }
        __syncthreads();
#pragma unroll
        for (int kk = 0; kk < 8; kk++) {
            float a[8], b[8];
            *(float4*)(a)     = *(const float4*)&As[kk][ty*8];
            *(float4*)(a + 4) = *(const float4*)&As[kk][ty*8 + 4];
            *(float4*)(b)     = *(const float4*)&Bs[kk][tx*8];
            *(float4*)(b + 4) = *(const float4*)&Bs[kk][tx*8 + 4];
#pragma unroll
            for (int i = 0; i < 8; i++)
#pragma unroll
                for (int j = 0; j < 8; j++)
                    c[i][j] = fmaf(a[i], b[j], c[i][j]);
        }
        __syncthreads();
    }
#pragma unroll
    for (int i = 0; i < 8; i++) {
        int co = coBase + ty*8 + i;
        float bb = bconv[co];
        float4 v0, v1;
        float* dst = &g_feat[co*HWI + h*WWD + tx*8];
        float t0 = c[i][0]+bb, t1 = c[i][1]+bb, t2 = c[i][2]+bb, t3 = c[i][3]+bb;
        float t4 = c[i][4]+bb, t5 = c[i][5]+bb, t6 = c[i][6]+bb, t7 = c[i][7]+bb;
        v0 = make_float4(fmaxf(t0,0.f), fmaxf(t1,0.f), fmaxf(t2,0.f), fmaxf(t3,0.f));
        v1 = make_float4(fmaxf(t4,0.f), fmaxf(t5,0.f), fmaxf(t6,0.f), fmaxf(t7,0.f));
        *(float4*)dst       = v0;
        *(float4*)(dst + 4) = v1;
    }
}

// =====================================================================
// 3) 1x1 heads: 54 outputs (18 score + 36 loc) per position, K=512.
//    Writes NHWC-interleaved straight into d_out regions.
// =====================================================================
__global__ void head_gemm(const float* __restrict__ Wsc, const float* __restrict__ bsc,
                          const float* __restrict__ Wlc, const float* __restrict__ blc,
                          float* __restrict__ out) {
    __shared__ float ws[54*64];
    int h = blockIdx.x, w = threadIdx.x;
    float acc[54];
#pragma unroll
    for (int o = 0; o < 54; o++) acc[o] = 0.f;
    for (int c0 = 0; c0 < CMID; c0 += 64) {
        for (int j = threadIdx.x; j < 54*64; j += blockDim.x) {
            int o = j >> 6, ci = j & 63;
            ws[j] = (o < 18) ? Wsc[o*CMID + c0 + ci] : Wlc[(o - 18)*CMID + c0 + ci];
        }
        __syncthreads();
        for (int ci = 0; ci < 64; ci++) {
            float f = g_feat[(c0 + ci)*HWI + h*WWD + w];
#pragma unroll
            for (int o = 0; o < 54; o++) acc[o] = fmaf(f, ws[o*64 + ci], acc[o]);
        }
        __syncthreads();
    }
    int p = h*WWD + w;
#pragma unroll
    for (int o = 0; o < 18; o++) out[p*18 + o] = acc[o] + bsc[o];
#pragma unroll
    for (int o = 0; o < 36; o++) out[LOC_OFF + p*36 + o] = acc[18 + o] + blc[o];
}

// =====================================================================
// 4) per-anchor: softmax fg, loc2bbox, clip, min-size filter, key + hist1
// =====================================================================
__global__ void prep_k(const float* __restrict__ out, const float* __restrict__ anch,
                       const int* __restrict__ img, const float* __restrict__ scale) {
    __shared__ unsigned sh[4096];
    for (int i = threadIdx.x; i < 4096; i += blockDim.x) sh[i] = 0;
    __syncthreads();
    int i = blockIdx.x*blockDim.x + threadIdx.x;   // exactly NANCH threads
    {
        int p = i / 9, a = i - p*9;
        float s0 = out[p*18 + a*2], s1 = out[p*18 + a*2 + 1];
        float m = fmaxf(s0, s1);
        float e0 = expf(s0 - m), e1 = expf(s1 - m);
        float fg = e1 / (e0 + e1);
        const float* lp = out + LOC_OFF + p*36 + a*4;
        float dy = lp[0], dx = lp[1], dh = lp[2], dw = lp[3];
        float ay1 = anch[i*4], ax1 = anch[i*4+1], ay2 = anch[i*4+2], ax2 = anch[i*4+3];
        float ahh = ay2 - ay1, aww = ax2 - ax1;
        float acy = ay1 + 0.5f*ahh, acx = ax1 + 0.5f*aww;
        float cy = dy*ahh + acy, cx = dx*aww + acx;
        float bh = expf(dh)*ahh, bw = expf(dw)*aww;
        float imh = (float)img[0], imw = (float)img[1];
        float y1 = fminf(fmaxf(cy - 0.5f*bh, 0.f), imh);
        float x1 = fminf(fmaxf(cx - 0.5f*bw, 0.f), imw);
        float y2 = fminf(fmaxf(cy + 0.5f*bh, 0.f), imh);
        float x2 = fminf(fmaxf(cx + 0.5f*bw, 0.f), imw);
        g_boxes4[i] = make_float4(y1, x1, y2, x2);
        float ms = 16.0f * scale[0];
        bool valid = ((y2 - y1) >= ms) && ((x2 - x1) >= ms);
        float sc = valid ? fg : -1e9f;
        unsigned u = __float_as_uint(sc);
        u = (u & 0x80000000u) ? ~u : (u | 0x80000000u);   // monotonic float->uint
        g_key[i] = u;
        atomicAdd(&sh[u >> 20], 1u);
    }
    __syncthreads();
    for (int b = threadIdx.x; b < 4096; b += blockDim.x)
        if (sh[b]) atomicAdd(&g_hist1[b], sh[b]);
}

// =====================================================================
// 5) radix-threshold selection (two 12-bit levels) for exact top-6000 superset
// =====================================================================
__global__ void scan1_k() {
    __shared__ unsigned seg[32];
    int t = threadIdx.x;
    unsigned s = 0;
    for (int b = 0; b < 128; b++) s += g_hist1[t*128 + b];
    seg[t] = s;
    __syncwarp();
    if (t == 0) {
        unsigned target = PRE, cum = 0; int si = 31;
        for (; si >= 0; si--) { if (cum + seg[si] >= target) break; cum += seg[si]; }
        if (si < 0) si = 0;
        unsigned c2 = cum; unsigned b1 = si*128;
        for (int b = si*128 + 127; b >= si*128; b--) {
            unsigned hv = g_hist1[b];
            if (c2 + hv >= target) { b1 = b; break; }
            c2 += hv;
        }
        g_ctrl.b1 = b1; g_ctrl.cAbove1 = c2;
    }
}

__global__ void hist2_k() {
    int i = blockIdx.x*blockDim.x + threadIdx.x;
    unsigned u = g_key[i];
    if ((u >> 20) == g_ctrl.b1) atomicAdd(&g_hist2[(u >> 8) & 0xFFFu], 1u);
}

__global__ void scan2_k() {
    __shared__ unsigned seg[32];
    int t = threadIdx.x;
    unsigned s = 0;
    for (int b = 0; b < 128; b++) s += g_hist2[t*128 + b];
    seg[t] = s;
    __syncwarp();
    if (t == 0) {
        unsigned target = PRE - g_ctrl.cAbove1, cum = 0; int si = 31;
        for (; si >= 0; si--) { if (cum + seg[si] >= target) break; cum += seg[si]; }
        if (si < 0) si = 0;
        unsigned c2 = cum; unsigned b2 = si*128;
        for (int b = si*128 + 127; b >= si*128; b--) {
            unsigned hv = g_hist2[b];
            if (c2 + hv >= target) { b2 = b; break; }
            c2 += hv;
        }
        g_ctrl.thresholdKey = (g_ctrl.b1 << 20) | (b2 << 8);
    }
}

__global__ void compact_k() {
    int i = blockIdx.x*blockDim.x + threadIdx.x;
    unsigned u = g_key[i];
    if (u >= g_ctrl.thresholdKey) {
        int pos = atomicAdd(&g_ctrl.candCount, 1);
        if (pos < 8192)
            g_cand[pos] = ((unsigned long long)(~u) << 32) | (unsigned)i;
    }
}

// =====================================================================
// 6) single-block bitonic sort of <=8192 u64 keys (score desc, index asc),
//    then gather boxes in top-k order. Exactly matches lax.top_k order.
// =====================================================================
__global__ void bitonic_k() {
    extern __shared__ unsigned long long shm[];
    int tid = threadIdx.x;
    int n = g_ctrl.candCount; if (n > 8192) n = 8192;
    for (int i = tid; i < 8192; i += 1024)
        shm[i] = (i < n) ? g_cand[i] : 0xFFFFFFFFFFFFFFFFull;
    __syncthreads();
    for (int k = 2; k <= 8192; k <<= 1) {
        for (int j = k >> 1; j > 0; j >>= 1) {
            for (int e = tid; e < 8192; e += 1024) {
                int p = e ^ j;
                if (p > e) {
                    unsigned long long a = shm[e], b = shm[p];
                    bool up = ((e & k) == 0);
                    if (up ? (a > b) : (a < b)) { shm[e] = b; shm[p] = a; }
                }
            }
            __syncthreads();
        }
    }
    for (int r = tid; r < PRE; r += 1024) {
        unsigned idx = (unsigned)shm[r];
        g_sorted[r] = g_boxes4[idx];
    }
}

// =====================================================================
// 7) IoU suppression bitmask: mask[i][wordX] bit jj set iff j>i && IoU>0.7
// =====================================================================
__global__ void mask_k() {
    int bx = blockIdx.x, by = blockIdx.y;
    if (bx < by) return;
    __shared__ float4 cb[64];
    int t = threadIdx.x;
    int j0 = bx * 64;
    {
        int j = j0 + t;
        cb[t] = (j < PRE) ? g_sorted[j] : make_float4(0, 0, 0, 0);
    }
    __syncthreads();
    int i = by*64 + t;
    if (i >= PRE) return;
    float4 bi = g_sorted[i];
    float areai = (bi.z - bi.x)*(bi.w - bi.y);
    unsigned long long word = 0;
#pragma unroll 4
    for (int jj = 0; jj < 64; jj++) {
        int j = j0 + jj;
        if (j > i && j < PRE) {
            float4 bj = cb[jj];
            float tly = fmaxf(bi.x, bj.x), tlx = fmaxf(bi.y, bj.y);
            float bry = fminf(bi.z, bj.z), brx = fminf(bi.w, bj.w);
            float hv = fmaxf(bry - tly, 0.f), wv = fmaxf(brx - tlx, 0.f);
            float inter = hv * wv;
            float areaj = (bj.z - bj.x)*(bj.w - bj.y);
            float iou = inter / (areai + areaj - inter + 1e-9f);
            if (iou > 0.7f) word |= (1ull << jj);
        }
    }
    g_mask[(size_t)i*NW + bx] = word;
}

// =====================================================================
// 8) exact serial-greedy NMS reduce: 64-box chunks; intra-chunk chain via
//    warp shuffles (registers), inter-chunk suppression OR'd in parallel.
// =====================================================================
__global__ void nms_reduce_k() {
    __shared__ unsigned long long removed[NW];
    __shared__ unsigned long long kbSh;
    int tid = threadIdx.x;
    for (int i = tid; i < NW; i += blockDim.x) removed[i] = 0;
    __syncthreads();
    for (int c = 0; c < NW; c++) {
        if (tid < 32) {
            int ra = c*64 + tid, rb = ra + 32;
            unsigned long long ia = (ra < PRE) ? g_mask[(size_t)ra*NW + c] : 0ull;
            unsigned long long ib = (rb < PRE) ? g_mask[(size_t)rb*NW + c] : 0ull;
            unsigned long long rw = removed[c];
            unsigned long long kb = 0;
#pragma unroll
            for (int k = 0; k < 32; k++) {
                unsigned long long mk = __shfl_sync(0xffffffffu, ia, k);
                if ((c*64 + k) < PRE && !((rw >> k) & 1ull)) { kb |= (1ull << k); rw |= mk; }
            }
#pragma unroll
            for (int k = 0; k < 32; k++) {
                unsigned long long mk = __shfl_sync(0xffffffffu, ib, k);
                int k2 = k + 32;
                if ((c*64 + k2) < PRE && !((rw >> k2) & 1ull)) { kb |= (1ull << k2); rw |= mk; }
            }
            if (tid == 0) { kbSh = kb; g_keep[c] = kb; }
        }
        __syncthreads();
        unsigned long long kb = kbSh;
        int slots = (NW - 1 - c) * 2;
        for (int slot = tid; slot < slots; slot += blockDim.x) {
            int w  = c + 1 + (slot >> 1);
            int k0 = (slot & 1) * 32;
            unsigned hk = (unsigned)(kb >> k0);
            unsigned long long acc = 0;
            while (hk) {
                int k = __ffs(hk) - 1; hk &= hk - 1;
                acc |= g_mask[(size_t)(c*64 + k0 + k)*NW + w];
            }
            if (acc) atomicOr(&removed[w], acc);
        }
        __syncthreads();
    }
}

// =====================================================================
// 9) rois output: kept boxes in score order, zero-padded to 300
// =====================================================================
__global__ void rois_k(float* __restrict__ out) {
    __shared__ int list[POST];
    __shared__ int nkS;
    if (threadIdx.x == 0) {
        int nk = 0;
        for (int w = 0; w < NW && nk < POST; w++) {
            unsigned long long bits = g_keep[w];
            while (bits && nk < POST) {
                int k = __ffsll(bits) - 1; bits &= bits - 1;
                list[nk++] = w*64 + k;
            }
        }
        nkS = nk;
    }
    __syncthreads();
    int nk = nkS;
    for (int r = threadIdx.x; r < POST; r += blockDim.x) {
        float4 v = make_float4(0, 0, 0, 0);
        if (r < nk) v = g_sorted[list[r]];
        *(float4*)(out + ROI_OFF + r*4) = v;
    }
}

// =====================================================================
extern "C" void kernel_launch(void* const* d_in, const int* in_sizes, int n_in,
                              void* d_out, int out_size) {
    const float* x     = (const float*)d_in[0];
    const float* anch  = (const float*)d_in[1];
    const int*   img   = (const int*)  d_in[2];
    const float* scale = (const float*)d_in[3];
    const float* Wc    = (const float*)d_in[4];
    const float* bc    = (const float*)d_in[5];
    const float* Wsc   = (const float*)d_in[6];
    const float* bsc   = (const float*)d_in[7];
    const float* Wlc   = (const float*)d_in[8];
    const float* blc   = (const float*)d_in[9];
    float* out = (float*)d_out;

    zero_ctrl_k<<<16, 256>>>();
    reorder_w<<<KKT, 128>>>(Wc);
    conv_gemm<<<dim3(HH, 4), 256>>>(x, bc);
    head_gemm<<<HH, 128>>>(Wsc, bsc, Wlc, blc, out);
    prep_k<<<NANCH/256, 256>>>(out, anch, img, scale);
    scan1_k<<<1, 32>>>();
    hist2_k<<<NANCH/256, 256>>>();
    scan2_k<<<1, 32>>>();
    compact_k<<<NANCH/256, 256>>>();
    cudaFuncSetAttribute(bitonic_k, cudaFuncAttributeMaxDynamicSharedMemorySize, 8192*8);
    bitonic_k<<<1, 1024, 8192*8>>>();
    mask_k<<<dim3(NW, NW), 64>>>();
    nms_reduce_k<<<1, 256>>>();
    rois_k<<<1, 256>>>(out);
}

// round 2
// speedup vs baseline: 1.3854x; 1.3854x over previous
#include <cuda_runtime.h>
#include <cstdint>

#define HH   128
#define WWD  128
#define HWI  (HH*WWD)
#define CIN  1024
#define CMID 512
#define NAA  9
#define NANCH (HWI*NAA)    // 147456
#define PRE  6000
#define POST 300
#define NW   94            // ceil(6000/64)
#define LOC_OFF (NANCH*2)          // 294912
#define ROI_OFF (NANCH*2 + NANCH*4) // 884736

// conv GEMM config
#define BK 16
#define KP 3072            // kh*1024+ci
#define NSLICE (KP/BK)     // 192
#define AS_STRIDE 384      // per kk: 3 kw * 128 co
#define AS_BUF (BK*AS_STRIDE)   // 6144 floats
#define BS_ROW 136
#define BS_BUF (BK*BS_ROW)      // 2176 floats
#define SM_BS  (2*AS_BUF)       // 12288
#define SM_WSH (SM_BS + 2*BS_BUF) // 16640
#define SM_FLOATS (SM_WSH + 54*128) // 23552
#define SM_BYTES (SM_FLOATS*4)      // 94208

struct Ctrl {
    unsigned b1;
    unsigned cAbove1;
    unsigned thresholdKey;
    int      candCount;
};

// ---- static device scratch (no allocations allowed) ----
__device__ __align__(16) float g_Ar2[KP*3*CMID];      // 18.9 MB weights [k'][kw][co]
__device__ __align__(16) float g_Wh[54*CMID];         // head weights [o][c]
__device__ __align__(16) float g_part[4*HWI*54];      // 14.2 MB head partials [cotile][p][o]
__device__ float4 g_boxes4[NANCH];
__device__ unsigned g_key[NANCH];
__device__ unsigned g_hist1[4096];
__device__ unsigned g_hist2[4096];
__device__ unsigned long long g_cand[8192];
__device__ float4 g_sorted[PRE];
__device__ unsigned long long g_mask[(size_t)PRE*NW];
__device__ unsigned long long g_keep[NW];
__device__ Ctrl g_ctrl;

// =====================================================================
__global__ void zero_ctrl_k() {
    int t = blockIdx.x*blockDim.x + threadIdx.x;
    if (t < 4096) { g_hist1[t] = 0; g_hist2[t] = 0; }
    if (t == 0) { g_ctrl.candCount = 0; g_ctrl.b1 = 0; g_ctrl.cAbove1 = 0; g_ctrl.thresholdKey = 0; }
}

// =====================================================================
// weight reorder: g_Ar2[(kh*1024+ci)*3 + kw][co] = Wc[co][ci][kh][kw]
// =====================================================================
__global__ void reorder2(const float* __restrict__ Wc) {
    int kp = blockIdx.x;             // 0..3071
    int kh = kp >> 10, ci = kp & 1023;
    for (int co = threadIdx.x; co < CMID; co += blockDim.x) {
        const float* s = Wc + ((size_t)co*CIN + ci)*9 + kh*3;
        float w0 = s[0], w1 = s[1], w2 = s[2];
        g_Ar2[(kp*3 + 0)*CMID + co] = w0;
        g_Ar2[(kp*3 + 1)*CMID + co] = w1;
        g_Ar2[(kp*3 + 2)*CMID + co] = w2;
    }
}

__global__ void build_wh(const float* __restrict__ Wsc, const float* __restrict__ Wlc) {
    int idx = blockIdx.x*blockDim.x + threadIdx.x;  // 54*512
    int o = idx >> 9;
    g_Wh[idx] = (o < 18) ? Wsc[idx] : Wlc[idx - 18*CMID];
}

// =====================================================================
// fused conv(3x3,1024->512)+bias+relu + 1x1 head partials
// implicit GEMM: M=512(co) x N=16384(p) x K'=3072(kh,ci), kw in registers
// tile 128co x 128w (one image row), 256 thr, 8x8/thr, cp.async dbl-buffer
// =====================================================================
__device__ __forceinline__ void cpasync16(float* dst, const float* src, int sz) {
    unsigned d = (unsigned)__cvta_generic_to_shared(dst);
    asm volatile("cp.async.cg.shared.global [%0], [%1], 16, %2;\n"
                 :: "r"(d), "l"(src), "r"(sz) : "memory");
}

__device__ __forceinline__ void load_slice(const float* __restrict__ X,
        float* As, float* Bs, int h, int coBase, int tid, int s, int buf) {
    int kh = s >> 6;                 // s/64 (16 | 1024 so kh constant per slice)
    int rowg = h + kh - 1;
    int sz  = (rowg >= 0 && rowg < HH) ? 16 : 0;
    int rowc = sz ? rowg : 0;
    float* Bb = Bs + buf*BS_BUF;
    float* Ab = As + buf*AS_BUF;
#pragma unroll
    for (int rq = 0; rq < 2; rq++) {
        int q = tid + rq*256;
        int row = q >> 5, c4 = (q & 31) << 2;
        int ci = s*BK + row - (kh << 10);
        const float* src = X + ci*HWI + rowc*WWD + c4;
        cpasync16(&Bb[row*BS_ROW + 4 + c4], src, sz);
    }
#pragma unroll
    for (int rq = 0; rq < 6; rq++) {
        int q = tid + rq*256;
        int kk = q/96, rem = q - kk*96;
        int kw = rem >> 5, c4 = (rem & 31) << 2;
        const float* src = g_Ar2 + (((s*BK + kk)*3 + kw) << 9) + coBase + c4;
        cpasync16(&Ab[kk*AS_STRIDE + (kw << 7) + c4], src, 16);
    }
    asm volatile("cp.async.commit_group;" ::: "memory");
}

__global__ void __launch_bounds__(256, 2)
conv_fused(const float* __restrict__ X, const float* __restrict__ bconv) {
    extern __shared__ float sm[];
    float* As  = sm;             // [2][16][3][128]
    float* Bs  = sm + SM_BS;     // [2][16][136]
    float* Wsh = sm + SM_WSH;    // [54][128]
    int h = blockIdx.x, coBase = blockIdx.y << 7;
    int tid = threadIdx.x;
    int ty = tid >> 4, tx = tid & 15;

    // stage head-weight slice for this co-tile
    for (int idx = tid; idx < 54*128; idx += 256)
        Wsh[idx] = g_Wh[(idx >> 7)*CMID + coBase + (idx & 127)];
    // zero Bs halo pads (never touched by cp.async)
    {
        int buf = tid >> 7, r = (tid >> 3) & 15, pz = tid & 7;
        int idx = (pz < 4) ? pz : 128 + pz;
        Bs[buf*BS_BUF + r*BS_ROW + idx] = 0.f;
    }

    float c[8][8];
#pragma unroll
    for (int i = 0; i < 8; i++)
#pragma unroll
        for (int j = 0; j < 8; j++) c[i][j] = 0.f;

    load_slice(X, As, Bs, h, coBase, tid, 0, 0);

    for (int s = 0; s < NSLICE; s++) {
        int buf = s & 1;
        if (s + 1 < NSLICE) {
            load_slice(X, As, Bs, h, coBase, tid, s + 1, buf ^ 1);
            asm volatile("cp.async.wait_group 1;" ::: "memory");
        } else {
            asm volatile("cp.async.wait_group 0;" ::: "memory");
        }
        __syncthreads();
        const float* Ab = As + buf*AS_BUF;
        const float* Bb = Bs + buf*BS_BUF;
#pragma unroll 4
        for (int kk = 0; kk < BK; kk++) {
            float b[16], a0[8], a1[8], a2[8];
            const float* br = Bb + kk*BS_ROW + tx*8;
            *(float4*)(b)      = *(const float4*)(br);
            *(float4*)(b + 4)  = *(const float4*)(br + 4);
            *(float4*)(b + 8)  = *(const float4*)(br + 8);
            *(float4*)(b + 12) = *(const float4*)(br + 12);
            const float* ar = Ab + kk*AS_STRIDE + ty*8;
            *(float4*)(a0)     = *(const float4*)(ar);
            *(float4*)(a0 + 4) = *(const float4*)(ar + 4);
            *(float4*)(a1)     = *(const float4*)(ar + 128);
            *(float4*)(a1 + 4) = *(const float4*)(ar + 132);
            *(float4*)(a2)     = *(const float4*)(ar + 256);
            *(float4*)(a2 + 4) = *(const float4*)(ar + 260);
#pragma unroll
            for (int i = 0; i < 8; i++)
#pragma unroll
                for (int j = 0; j < 8; j++) {
                    c[i][j] = fmaf(a0[i], b[j + 3], c[i][j]);
                    c[i][j] = fmaf(a1[i], b[j + 4], c[i][j]);
                    c[i][j] = fmaf(a2[i], b[j + 5], c[i][j]);
                }
        }
        __syncthreads();
    }

    // ---- epilogue: bias+relu -> shared feat tile (aliases buffers) ----
    float* Sfeat = sm;   // [128co][128p], Wsh region untouched
#pragma unroll
    for (int i = 0; i < 8; i++) {
        int co = ty*8 + i;
        float bb = bconv[coBase + co];
        float4 v0 = make_float4(fmaxf(c[i][0]+bb,0.f), fmaxf(c[i][1]+bb,0.f),
                                fmaxf(c[i][2]+bb,0.f), fmaxf(c[i][3]+bb,0.f));
        float4 v1 = make_float4(fmaxf(c[i][4]+bb,0.f), fmaxf(c[i][5]+bb,0.f),
                                fmaxf(c[i][6]+bb,0.f), fmaxf(c[i][7]+bb,0.f));
        *(float4*)&Sfeat[co*128 + tx*8]     = v0;
        *(float4*)&Sfeat[co*128 + tx*8 + 4] = v1;
    }
    __syncthreads();

    // ---- head partials: 54 outs x 128 p over this co-tile's 128 channels ----
    int p = tid & 127, oHalf = tid >> 7;
    float acc[27];
#pragma unroll
    for (int i = 0; i < 27; i++) acc[i] = 0.f;
    const float* Wrow = Wsh + oHalf*27*128;
    for (int co = 0; co < 128; co++) {
        float f = Sfeat[co*128 + p];
#pragma unroll
        for (int i = 0; i < 27; i++)
            acc[i] = fmaf(f, Wrow[i*128 + co], acc[i]);
    }
    float* dst = g_part + ((size_t)(blockIdx.y*HWI + h*WWD + p))*54 + oHalf*27;
#pragma unroll
    for (int i = 0; i < 27; i++) dst[i] = acc[i];
}

// =====================================================================
// per-anchor: reduce head partials, write score/loc outputs, softmax fg,
// loc2bbox, clip, min-size filter, key + hist1
// =====================================================================
__global__ void prep_k(const float* __restrict__ anch,
                       const int* __restrict__ img, const float* __restrict__ scale,
                       const float* __restrict__ bsc, const float* __restrict__ blc,
                       float* __restrict__ out) {
    __shared__ unsigned sh[4096];
    for (int i = threadIdx.x; i < 4096; i += blockDim.x) sh[i] = 0;
    __syncthreads();
    int i = blockIdx.x*blockDim.x + threadIdx.x;   // exactly NANCH threads
    {
        int p = i / 9, a = i - p*9;
        float s0 = bsc[2*a], s1 = bsc[2*a + 1];
        float dy = blc[4*a], dx = blc[4*a+1], dh = blc[4*a+2], dw = blc[4*a+3];
#pragma unroll
        for (int t = 0; t < 4; t++) {
            const float* pp = g_part + ((size_t)(t*HWI + p))*54;
            s0 += pp[2*a];      s1 += pp[2*a + 1];
            dy += pp[18 + 4*a]; dx += pp[18 + 4*a + 1];
            dh += pp[18 + 4*a + 2]; dw += pp[18 + 4*a + 3];
        }
        out[p*18 + 2*a]     = s0;
        out[p*18 + 2*a + 1] = s1;
        float* lo = out + LOC_OFF + p*36 + 4*a;
        lo[0] = dy; lo[1] = dx; lo[2] = dh; lo[3] = dw;

        float m = fmaxf(s0, s1);
        float e0 = expf(s0 - m), e1 = expf(s1 - m);
        float fg = e1 / (e0 + e1);
        float ay1 = anch[i*4], ax1 = anch[i*4+1], ay2 = anch[i*4+2], ax2 = anch[i*4+3];
        float ahh = ay2 - ay1, aww = ax2 - ax1;
        float acy = ay1 + 0.5f*ahh, acx = ax1 + 0.5f*aww;
        float cy = dy*ahh + acy, cx = dx*aww + acx;
        float bh = expf(dh)*ahh, bw = expf(dw)*aww;
        float imh = (float)img[0], imw = (float)img[1];
        float y1 = fminf(fmaxf(cy - 0.5f*bh, 0.f), imh);
        float x1 = fminf(fmaxf(cx - 0.5f*bw, 0.f), imw);
        float y2 = fminf(fmaxf(cy + 0.5f*bh, 0.f), imh);
        float x2 = fminf(fmaxf(cx + 0.5f*bw, 0.f), imw);
        g_boxes4[i] = make_float4(y1, x1, y2, x2);
        float ms = 16.0f * scale[0];
        bool valid = ((y2 - y1) >= ms) && ((x2 - x1) >= ms);
        float sc = valid ? fg : -1e9f;
        unsigned u = __float_as_uint(sc);
        u = (u & 0x80000000u) ? ~u : (u | 0x80000000u);
        g_key[i] = u;
        atomicAdd(&sh[u >> 20], 1u);
    }
    __syncthreads();
    for (int b = threadIdx.x; b < 4096; b += blockDim.x)
        if (sh[b]) atomicAdd(&g_hist1[b], sh[b]);
}

// =====================================================================
// radix-threshold selection (two 12-bit levels)
// =====================================================================
__global__ void scan1_k() {
    __shared__ unsigned seg[32];
    int t = threadIdx.x;
    unsigned s = 0;
    for (int b = 0; b < 128; b++) s += g_hist1[t*128 + b];
    seg[t] = s;
    __syncwarp();
    if (t == 0) {
        unsigned target = PRE, cum = 0; int si = 31;
        for (; si >= 0; si--) { if (cum + seg[si] >= target) break; cum += seg[si]; }
        if (si < 0) si = 0;
        unsigned c2 = cum; unsigned b1 = si*128;
        for (int b = si*128 + 127; b >= si*128; b--) {
            unsigned hv = g_hist1[b];
            if (c2 + hv >= target) { b1 = b; break; }
            c2 += hv;
        }
        g_ctrl.b1 = b1; g_ctrl.cAbove1 = c2;
    }
}

__global__ void hist2_k() {
    int i = blockIdx.x*blockDim.x + threadIdx.x;
    unsigned u = g_key[i];
    if ((u >> 20) == g_ctrl.b1) atomicAdd(&g_hist2[(u >> 8) & 0xFFFu], 1u);
}

__global__ void scan2_k() {
    __shared__ unsigned seg[32];
    int t = threadIdx.x;
    unsigned s = 0;
    for (int b = 0; b < 128; b++) s += g_hist2[t*128 + b];
    seg[t] = s;
    __syncwarp();
    if (t == 0) {
        unsigned target = PRE - g_ctrl.cAbove1, cum = 0; int si = 31;
        for (; si >= 0; si--) { if (cum + seg[si] >= target) break; cum += seg[si]; }
        if (si < 0) si = 0;
        unsigned c2 = cum; unsigned b2 = si*128;
        for (int b = si*128 + 127; b >= si*128; b--) {
            unsigned hv = g_hist2[b];
            if (c2 + hv >= target) { b2 = b; break; }
            c2 += hv;
        }
        g_ctrl.thresholdKey = (g_ctrl.b1 << 20) | (b2 << 8);
    }
}

__global__ void compact_k() {
    int i = blockIdx.x*blockDim.x + threadIdx.x;
    unsigned u = g_key[i];
    if (u >= g_ctrl.thresholdKey) {
        int pos = atomicAdd(&g_ctrl.candCount, 1);
        if (pos < 8192)
            g_cand[pos] = ((unsigned long long)(~u) << 32) | (unsigned)i;
    }
}

// =====================================================================
// single-block bitonic sort (score desc, index asc) -> exact lax.top_k order
// =====================================================================
__global__ void bitonic_k() {
    extern __shared__ unsigned long long shm[];
    int tid = threadIdx.x;
    int n = g_ctrl.candCount; if (n > 8192) n = 8192;
    for (int i = tid; i < 8192; i += 1024)
        shm[i] = (i < n) ? g_cand[i] : 0xFFFFFFFFFFFFFFFFull;
    __syncthreads();
    for (int k = 2; k <= 8192; k <<= 1) {
        for (int j = k >> 1; j > 0; j >>= 1) {
            for (int e = tid; e < 8192; e += 1024) {
                int p = e ^ j;
                if (p > e) {
                    unsigned long long a = shm[e], b = shm[p];
                    bool up = ((e & k) == 0);
                    if (up ? (a > b) : (a < b)) { shm[e] = b; shm[p] = a; }
                }
            }
            __syncthreads();
        }
    }
    for (int r = tid; r < PRE; r += 1024) {
        unsigned idx = (unsigned)shm[r];
        g_sorted[r] = g_boxes4[idx];
    }
}

// =====================================================================
// IoU suppression bitmask
// =====================================================================
__global__ void mask_k() {
    int bx = blockIdx.x, by = blockIdx.y;
    if (bx < by) return;
    __shared__ float4 cb[64];
    int t = threadIdx.x;
    int j0 = bx * 64;
    {
        int j = j0 + t;
        cb[t] = (j < PRE) ? g_sorted[j] : make_float4(0, 0, 0, 0);
    }
    __syncthreads();
    int i = by*64 + t;
    if (i >= PRE) return;
    float4 bi = g_sorted[i];
    float areai = (bi.z - bi.x)*(bi.w - bi.y);
    unsigned long long word = 0;
#pragma unroll 4
    for (int jj = 0; jj < 64; jj++) {
        int j = j0 + jj;
        if (j > i && j < PRE) {
            float4 bj = cb[jj];
            float tly = fmaxf(bi.x, bj.x), tlx = fmaxf(bi.y, bj.y);
            float bry = fminf(bi.z, bj.z), brx = fminf(bi.w, bj.w);
            float hv = fmaxf(bry - tly, 0.f), wv = fmaxf(brx - tlx, 0.f);
            float inter = hv * wv;
            float areaj = (bj.z - bj.x)*(bj.w - bj.y);
            float iou = inter / (areai + areaj - inter + 1e-9f);
            if (iou > 0.7f) word |= (1ull << jj);
        }
    }
    g_mask[(size_t)i*NW + bx] = word;
}

// =====================================================================
// exact serial-greedy NMS reduce
// =====================================================================
__global__ void nms_reduce_k() {
    __shared__ unsigned long long removed[NW];
    __shared__ unsigned long long kbSh;
    int tid = threadIdx.x;
    for (int i = tid; i < NW; i += blockDim.x) removed[i] = 0;
    __syncthreads();
    for (int c = 0; c < NW; c++) {
        if (tid < 32) {
            int ra = c*64 + tid, rb = ra + 32;
            unsigned long long ia = (ra < PRE) ? g_mask[(size_t)ra*NW + c] : 0ull;
            unsigned long long ib = (rb < PRE) ? g_mask[(size_t)rb*NW + c] : 0ull;
            unsigned long long rw = removed[c];
            unsigned long long kb = 0;
#pragma unroll
            for (int k = 0; k < 32; k++) {
                unsigned long long mk = __shfl_sync(0xffffffffu, ia, k);
                if ((c*64 + k) < PRE && !((rw >> k) & 1ull)) { kb |= (1ull << k); rw |= mk; }
            }
#pragma unroll
            for (int k = 0; k < 32; k++) {
                unsigned long long mk = __shfl_sync(0xffffffffu, ib, k);
                int k2 = k + 32;
                if ((c*64 + k2) < PRE && !((rw >> k2) & 1ull)) { kb |= (1ull << k2); rw |= mk; }
            }
            if (tid == 0) { kbSh = kb; g_keep[c] = kb; }
        }
        __syncthreads();
        unsigned long long kb = kbSh;
        int slots = (NW - 1 - c) * 2;
        for (int slot = tid; slot < slots; slot += blockDim.x) {
            int w  = c + 1 + (slot >> 1);
            int k0 = (slot & 1) * 32;
            unsigned hk = (unsigned)(kb >> k0);
            unsigned long long acc = 0;
            while (hk) {
                int k = __ffs(hk) - 1; hk &= hk - 1;
                acc |= g_mask[(size_t)(c*64 + k0 + k)*NW + w];
            }
            if (acc) atomicOr(&removed[w], acc);
        }
        __syncthreads();
    }
}

// =====================================================================
__global__ void rois_k(float* __restrict__ out) {
    __shared__ int list[POST];
    __shared__ int nkS;
    if (threadIdx.x == 0) {
        int nk = 0;
        for (int w = 0; w < NW && nk < POST; w++) {
            unsigned long long bits = g_keep[w];
            while (bits && nk < POST) {
                int k = __ffsll(bits) - 1; bits &= bits - 1;
                list[nk++] = w*64 + k;
            }
        }
        nkS = nk;
    }
    __syncthreads();
    int nk = nkS;
    for (int r = threadIdx.x; r < POST; r += blockDim.x) {
        float4 v = make_float4(0, 0, 0, 0);
        if (r < nk) v = g_sorted[list[r]];
        *(float4*)(out + ROI_OFF + r*4) = v;
    }
}

// =====================================================================
extern "C" void kernel_launch(void* const* d_in, const int* in_sizes, int n_in,
                              void* d_out, int out_size) {
    const float* x     = (const float*)d_in[0];
    const float* anch  = (const float*)d_in[1];
    const int*   img   = (const int*)  d_in[2];
    const float* scale = (const float*)d_in[3];
    const float* Wc    = (const float*)d_in[4];
    const float* bc    = (const float*)d_in[5];
    const float* Wsc   = (const float*)d_in[6];
    const float* bsc   = (const float*)d_in[7];
    const float* Wlc   = (const float*)d_in[8];
    const float* blc   = (const float*)d_in[9];
    float* out = (float*)d_out;

    zero_ctrl_k<<<16, 256>>>();
    reorder2<<<KP, 128>>>(Wc);
    build_wh<<<54, 512>>>(Wsc, Wlc);
    cudaFuncSetAttribute(conv_fused, cudaFuncAttributeMaxDynamicSharedMemorySize, SM_BYTES);
    conv_fused<<<dim3(HH, 4), 256, SM_BYTES>>>(x, bc);
    prep_k<<<NANCH/256, 256>>>(anch, img, scale, bsc, blc, out);
    scan1_k<<<1, 32>>>();
    hist2_k<<<NANCH/256, 256>>>();
    scan2_k<<<1, 32>>>();
    compact_k<<<NANCH/256, 256>>>();
    cudaFuncSetAttribute(bitonic_k, cudaFuncAttributeMaxDynamicSharedMemorySize, 8192*8);
    bitonic_k<<<1, 1024, 8192*8>>>();
    mask_k<<<dim3(NW, NW), 64>>>();
    nms_reduce_k<<<1, 256>>>();
    rois_k<<<1, 256>>>(out);
}